// round 4
// baseline (speedup 1.0000x reference)
#include <cuda_runtime.h>
#include <cuda_bf16.h>
#include <cstdint>
#include <cstddef>

#define S_LEN 2048
#define B_DIM 8
#define E_DIM 1024
#define M_TOT (S_LEN*B_DIM)      // 16384
#define CH    (B_DIM*E_DIM)      // 8192
#define NCHUNK 16
#define CLEN  (S_LEN/NCHUNK)     // 128

// ---------------- scratch (device globals; no allocation allowed) ------------
__device__ __nv_bfloat16 g_xk_hi[(size_t)M_TOT*E_DIM];
__device__ __nv_bfloat16 g_xk_lo[(size_t)M_TOT*E_DIM];
__device__ __nv_bfloat16 g_xv_hi[(size_t)M_TOT*E_DIM];
__device__ __nv_bfloat16 g_xv_lo[(size_t)M_TOT*E_DIM];
__device__ __nv_bfloat16 g_r_hi [(size_t)M_TOT*E_DIM];
__device__ __nv_bfloat16 g_r_lo [(size_t)M_TOT*E_DIM];
__device__ float g_k [(size_t)M_TOT*E_DIM];
__device__ float g_v [(size_t)M_TOT*E_DIM];
__device__ __nv_bfloat16 g_wkt_hi[(size_t)E_DIM*E_DIM];
__device__ __nv_bfloat16 g_wkt_lo[(size_t)E_DIM*E_DIM];
__device__ __nv_bfloat16 g_wvt_hi[(size_t)E_DIM*E_DIM];
__device__ __nv_bfloat16 g_wvt_lo[(size_t)E_DIM*E_DIM];
__device__ __nv_bfloat16 g_wot_hi[(size_t)E_DIM*E_DIM];
__device__ __nv_bfloat16 g_wot_lo[(size_t)E_DIM*E_DIM];
__device__ float g_agg[3*NCHUNK*CH];
__device__ float g_pre[3*NCHUNK*CH];

// ---------------- helpers ----------------------------------------------------
__device__ __forceinline__ uint32_t smem_addr(const void* p) {
    uint32_t a;
    asm("{ .reg .u64 t; cvta.to.shared.u64 t, %1; cvt.u32.u64 %0, t; }" : "=r"(a) : "l"(p));
    return a;
}
#define CP_ASYNC16(dst, src) \
    asm volatile("cp.async.cg.shared.global [%0], [%1], 16;" :: "r"(dst), "l"(src) : "memory")
#define CP_COMMIT() asm volatile("cp.async.commit_group;" ::: "memory")
#define CP_WAIT(n)  asm volatile("cp.async.wait_group %0;" :: "n"(n) : "memory")

#define LDSM4(r, addr) \
    asm volatile("ldmatrix.sync.aligned.m8n8.x4.shared.b16 {%0,%1,%2,%3}, [%4];" \
        : "=r"((r)[0]), "=r"((r)[1]), "=r"((r)[2]), "=r"((r)[3]) : "r"(addr))

__device__ __forceinline__ void mma_bf16(float c[4], const uint32_t a[4], const uint32_t b[2]) {
    asm volatile(
        "mma.sync.aligned.m16n8k16.row.col.f32.bf16.bf16.f32 "
        "{%0,%1,%2,%3}, {%4,%5,%6,%7}, {%8,%9}, {%0,%1,%2,%3};\n"
        : "+f"(c[0]), "+f"(c[1]), "+f"(c[2]), "+f"(c[3])
        : "r"(a[0]), "r"(a[1]), "r"(a[2]), "r"(a[3]), "r"(b[0]), "r"(b[1]));
}

__device__ __forceinline__ void bsplit(float v, __nv_bfloat16& h, __nv_bfloat16& l) {
    h = __float2bfloat16_rn(v);
    l = __float2bfloat16_rn(v - __bfloat162float(h));
}

// ============================================================
// 1) token mix + bf16 split
// ============================================================
__global__ void mix_split_kernel(const float* __restrict__ x,
                                 const float* __restrict__ tmrkv) {
    int i4  = blockIdx.x * blockDim.x + threadIdx.x;
    int idx = i4 * 4;
    int e   = idx & (E_DIM - 1);
    float4 xc = *(const float4*)(x + idx);
    float4 xp = make_float4(0.f, 0.f, 0.f, 0.f);
    if (idx >= CH) xp = *(const float4*)(x + idx - CH);
    float4 mk = *(const float4*)(tmrkv + E_DIM   + e);
    float4 mv = *(const float4*)(tmrkv + 2*E_DIM + e);
    float ok[4], ov[4];
    ok[0] = mk.x*xc.x + (1.f-mk.x)*xp.x;  ov[0] = mv.x*xc.x + (1.f-mv.x)*xp.x;
    ok[1] = mk.y*xc.y + (1.f-mk.y)*xp.y;  ov[1] = mv.y*xc.y + (1.f-mv.y)*xp.y;
    ok[2] = mk.z*xc.z + (1.f-mk.z)*xp.z;  ov[2] = mv.z*xc.z + (1.f-mv.z)*xp.z;
    ok[3] = mk.w*xc.w + (1.f-mk.w)*xp.w;  ov[3] = mv.w*xc.w + (1.f-mv.w)*xp.w;
    ushort4 kh, kl, vh, vl;
    __nv_bfloat16 h, l;
    bsplit(ok[0], h, l); kh.x = __bfloat16_as_ushort(h); kl.x = __bfloat16_as_ushort(l);
    bsplit(ok[1], h, l); kh.y = __bfloat16_as_ushort(h); kl.y = __bfloat16_as_ushort(l);
    bsplit(ok[2], h, l); kh.z = __bfloat16_as_ushort(h); kl.z = __bfloat16_as_ushort(l);
    bsplit(ok[3], h, l); kh.w = __bfloat16_as_ushort(h); kl.w = __bfloat16_as_ushort(l);
    bsplit(ov[0], h, l); vh.x = __bfloat16_as_ushort(h); vl.x = __bfloat16_as_ushort(l);
    bsplit(ov[1], h, l); vh.y = __bfloat16_as_ushort(h); vl.y = __bfloat16_as_ushort(l);
    bsplit(ov[2], h, l); vh.z = __bfloat16_as_ushort(h); vl.z = __bfloat16_as_ushort(l);
    bsplit(ov[3], h, l); vh.w = __bfloat16_as_ushort(h); vl.w = __bfloat16_as_ushort(l);
    *(ushort4*)((unsigned short*)g_xk_hi + idx) = kh;
    *(ushort4*)((unsigned short*)g_xk_lo + idx) = kl;
    *(ushort4*)((unsigned short*)g_xv_hi + idx) = vh;
    *(ushort4*)((unsigned short*)g_xv_lo + idx) = vl;
}

// ============================================================
// 2) weight transpose + split:  T[n][k] = split(W[k][n])
// ============================================================
__global__ void wsplit_kernel(const float* __restrict__ W,
                              __nv_bfloat16* __restrict__ Thi,
                              __nv_bfloat16* __restrict__ Tlo) {
    __shared__ float t[32][33];
    int bx = blockIdx.x * 32;   // n block
    int by = blockIdx.y * 32;   // k block
    int tx = threadIdx.x;
    for (int j = threadIdx.y; j < 32; j += 8)
        t[j][tx] = W[(size_t)(by + j) * E_DIM + bx + tx];
    __syncthreads();
    for (int j = threadIdx.y; j < 32; j += 8) {
        float v = t[tx][j];           // element (k=by+tx, n=bx+j)
        __nv_bfloat16 h, l; bsplit(v, h, l);
        size_t o = (size_t)(bx + j) * E_DIM + by + tx;
        Thi[o] = h; Tlo[o] = l;
    }
}

// ============================================================
// 3) split-bf16 GEMM via mma.sync m16n8k16 + ldmatrix + 3-stage cp.async
//    A: [M,K] bf16 hi/lo (K-major); B: [N,K] bf16 hi/lo (pre-transposed W)
// ============================================================
#define BM 128
#define BN 128
#define BK 32
#define STR 20                     // uint32 per smem row (16 data + 4 pad)
#define TILE_U (128*STR)           // 2560 u32 per operand tile
#define NSTG 3
#define STAGE_U (4*TILE_U)         // Ah,Al,Bh,Bl
#define GEMM_SMEM (NSTG*STAGE_U*4) // 122880 bytes

__global__ void __launch_bounds__(256)
gemm_bf16_split(const __nv_bfloat16* __restrict__ Ahi, const __nv_bfloat16* __restrict__ Alo,
                const __nv_bfloat16* __restrict__ Bhi, const __nv_bfloat16* __restrict__ Blo,
                float* __restrict__ C) {
    extern __shared__ uint32_t smem[];   // [NSTG][4][TILE_U]

    int tid  = threadIdx.x;
    int warp = tid >> 5, lane = tid & 31;
    int wm = warp & 3, wn = warp >> 2;             // 4 x 2 warps
    int bm = blockIdx.y * BM, bn = blockIdx.x * BN;

    const char* srcs[4] = {
        (const char*)(Ahi + (size_t)bm * E_DIM),
        (const char*)(Alo + (size_t)bm * E_DIM),
        (const char*)(Bhi + (size_t)bn * E_DIM),
        (const char*)(Blo + (size_t)bn * E_DIM) };
    uint32_t sbase = smem_addr(smem);

    auto load_tile = [&](int kt, int stg) {
        uint32_t dst0 = sbase + (uint32_t)stg * STAGE_U * 4;
        int koff = kt * BK * 2;    // byte offset along K
        #pragma unroll
        for (int arr = 0; arr < 4; arr++) {
            #pragma unroll
            for (int i = 0; i < 2; i++) {
                int f = tid + i*256;
                int row = f >> 2, ch = f & 3;
                uint32_t dst = dst0 + arr*TILE_U*4 + row*STR*4 + ch*16;
                const char* src = srcs[arr] + (size_t)row * (E_DIM*2) + koff + ch*16;
                CP_ASYNC16(dst, src);
            }
        }
    };

    // ---- ldmatrix lane addressing (byte offsets within an operand tile) ----
    int lm = lane & 7, lg = lane >> 3;   // lg = matrix index 0..3
    // A x4: m0(rows+0,k0-7) m1(rows+8,k0-7) m2(rows+0,k8-15) m3(rows+8,k8-15)
    uint32_t aoff[2];
    #pragma unroll
    for (int mt = 0; mt < 2; mt++)
        aoff[mt] = (uint32_t)(((wm*32 + mt*16 + (lg & 1)*8 + lm) * STR + (lg >> 1)*4) * 4);
    // B x4 per j: m0(n+0,k0-7)->b[2j][0]  m1(n+0,k8-15)->b[2j][1]
    //             m2(n+8,k0-7)->b[2j+1][0] m3(n+8,k8-15)->b[2j+1][1]
    uint32_t boff[4];
    #pragma unroll
    for (int j = 0; j < 4; j++)
        boff[j] = (uint32_t)(((wn*64 + j*16 + (lg >> 1)*8 + lm) * STR + (lg & 1)*4) * 4);

    float acc[2][8][4];
    #pragma unroll
    for (int mt = 0; mt < 2; mt++)
        #pragma unroll
        for (int nt = 0; nt < 8; nt++)
            #pragma unroll
            for (int q = 0; q < 4; q++) acc[mt][nt][q] = 0.f;

    const int NK = E_DIM / BK;   // 32
    load_tile(0, 0); CP_COMMIT();
    load_tile(1, 1); CP_COMMIT();

    for (int kt = 0; kt < NK; kt++) {
        int stg = kt % NSTG;
        if (kt == NK - 1) { CP_WAIT(0); } else { CP_WAIT(1); }
        __syncthreads();
        if (kt + 2 < NK) { load_tile(kt + 2, (kt + 2) % NSTG); CP_COMMIT(); }

        uint32_t tAh = sbase + (uint32_t)stg * STAGE_U * 4;
        uint32_t tAl = tAh + TILE_U*4;
        uint32_t tBh = tAh + 2*TILE_U*4;
        uint32_t tBl = tAh + 3*TILE_U*4;

        #pragma unroll
        for (int ks = 0; ks < 2; ks++) {
            uint32_t ksb = (uint32_t)(ks * 8 * 4);
            uint32_t ah[2][4], al[2][4], bh[8][2], bl[8][2];
            #pragma unroll
            for (int mt = 0; mt < 2; mt++) {
                LDSM4(ah[mt], tAh + aoff[mt] + ksb);
                LDSM4(al[mt], tAl + aoff[mt] + ksb);
            }
            #pragma unroll
            for (int j = 0; j < 4; j++) {
                uint32_t rb[4], rl[4];
                LDSM4(rb, tBh + boff[j] + ksb);
                bh[2*j][0] = rb[0]; bh[2*j][1] = rb[1];
                bh[2*j+1][0] = rb[2]; bh[2*j+1][1] = rb[3];
                LDSM4(rl, tBl + boff[j] + ksb);
                bl[2*j][0] = rl[0]; bl[2*j][1] = rl[1];
                bl[2*j+1][0] = rl[2]; bl[2*j+1][1] = rl[3];
            }
            #pragma unroll
            for (int mt = 0; mt < 2; mt++)
                #pragma unroll
                for (int nt = 0; nt < 8; nt++) {
                    mma_bf16(acc[mt][nt], ah[mt], bh[nt]);
                    mma_bf16(acc[mt][nt], ah[mt], bl[nt]);
                    mma_bf16(acc[mt][nt], al[mt], bh[nt]);
                }
        }
        __syncthreads();
    }

    #pragma unroll
    for (int mt = 0; mt < 2; mt++) {
        int r0 = bm + wm*32 + mt*16 + (lane >> 2);
        #pragma unroll
        for (int nt = 0; nt < 8; nt++) {
            int c0 = bn + wn*64 + nt*8 + ((lane & 3) << 1);
            *(float2*)(&C[(size_t) r0     *E_DIM + c0]) = make_float2(acc[mt][nt][0], acc[mt][nt][1]);
            *(float2*)(&C[(size_t)(r0 + 8)*E_DIM + c0]) = make_float2(acc[mt][nt][2], acc[mt][nt][3]);
        }
    }
}

// ============================================================
// 4) chunked associative exp-scan
// ============================================================
__global__ void scan_pass1(const float* __restrict__ time_decay) {
    int tid = blockIdx.x * blockDim.x + threadIdx.x;
    int c = tid / CH, ch = tid % CH;
    float w = time_decay[ch & (E_DIM - 1)];
    float a = 0.f, b = 0.f, p = -1e30f;
    int base = c * CLEN;
    for (int t0 = 0; t0 < CLEN; t0 += 8) {
        float kk[8], vv[8];
        #pragma unroll
        for (int i = 0; i < 8; i++) {
            size_t off = (size_t)(base + t0 + i) * CH + ch;
            kk[i] = g_k[off]; vv[i] = g_v[off];
        }
        #pragma unroll
        for (int i = 0; i < 8; i++) {
            float pw = p + w;
            float d  = pw - kk[i];
            float e  = __expf(-fabsf(d));
            float e1 = (d >= 0.f) ? 1.f : e;
            float e2 = (d >= 0.f) ? e   : 1.f;
            a = a*e1 + vv[i]*e2;
            b = b*e1 + e2;
            p = fmaxf(pw, kk[i]);
        }
    }
    g_agg[              c*CH + ch] = a;
    g_agg[  NCHUNK*CH + c*CH + ch] = b;
    g_agg[2*NCHUNK*CH + c*CH + ch] = p;
}

__global__ void scan_pass2(const float* __restrict__ time_decay) {
    int ch = blockIdx.x * blockDim.x + threadIdx.x;
    float w  = time_decay[ch & (E_DIM - 1)];
    float Lw = (float)CLEN * w;
    float a = 0.f, b = 0.f, p = -1e30f;
    for (int c = 0; c < NCHUNK; c++) {
        g_pre[              c*CH + ch] = a;
        g_pre[  NCHUNK*CH + c*CH + ch] = b;
        g_pre[2*NCHUNK*CH + c*CH + ch] = p;
        float a2 = g_agg[              c*CH + ch];
        float b2 = g_agg[  NCHUNK*CH + c*CH + ch];
        float p2 = g_agg[2*NCHUNK*CH + c*CH + ch];
        float pw = p + Lw;
        float d  = pw - p2;
        float e  = __expf(-fabsf(d));
        float e1 = (d >= 0.f) ? 1.f : e;
        float e2 = (d >= 0.f) ? e   : 1.f;
        a = a*e1 + a2*e2;
        b = b*e1 + b2*e2;
        p = fmaxf(pw, p2);
    }
}

__global__ void scan_pass3(const float* __restrict__ time_decay,
                           const float* __restrict__ time_first) {
    int tid = blockIdx.x * blockDim.x + threadIdx.x;
    int c = tid / CH, ch = tid % CH;
    int e0 = ch & (E_DIM - 1);
    float w = time_decay[e0];
    float u = time_first[e0];
    float a = g_pre[              c*CH + ch];
    float b = g_pre[  NCHUNK*CH + c*CH + ch];
    float p = g_pre[2*NCHUNK*CH + c*CH + ch];
    int base = c * CLEN;
    for (int t0 = 0; t0 < CLEN; t0 += 8) {
        float kk[8], vv[8];
        #pragma unroll
        for (int i = 0; i < 8; i++) {
            size_t off = (size_t)(base + t0 + i) * CH + ch;
            kk[i] = g_k[off]; vv[i] = g_v[off];
        }
        #pragma unroll
        for (int i = 0; i < 8; i++) {
            float pw = p + w;
            float d  = pw - kk[i];
            float e  = __expf(-fabsf(d));
            float e1 = (d >= 0.f) ? 1.f : e;
            float e2 = (d >= 0.f) ? e   : 1.f;
            a = a*e1 + vv[i]*e2;
            b = b*e1 + e2;
            p = fmaxf(pw, kk[i]);
            float kb = kk[i] + u + w;
            float d2 = p - kb;
            float eo = __expf(-fabsf(d2));
            float o1 = (d2 >= 0.f) ? 1.f : eo;
            float o2 = (d2 >= 0.f) ? eo  : 1.f;
            float cn = a*o1 + vv[i]*o2;
            float dn = b*o1 + o2;
            float q  = __fdividef(cn, dn);
            size_t off = (size_t)(base + t0 + i) * CH + ch;
            __nv_bfloat16 h, l; bsplit(q, h, l);
            g_r_hi[off] = h; g_r_lo[off] = l;
        }
    }
}

// ============================================================
// launch
// ============================================================
extern "C" void kernel_launch(void* const* d_in, const int* in_sizes, int n_in,
                              void* d_out, int out_size) {
    const float* x     = (const float*)d_in[0];
    const float* tmrkv = (const float*)d_in[1];
    const float* Wk    = (const float*)d_in[2];
    const float* Wv    = (const float*)d_in[3];
    const float* td    = (const float*)d_in[4];
    const float* tf    = (const float*)d_in[5];
    const float* Wout  = (const float*)d_in[6];
    float* out = (float*)d_out;

    cudaFuncSetAttribute(gemm_bf16_split,
                         cudaFuncAttributeMaxDynamicSharedMemorySize, GEMM_SMEM);

    __nv_bfloat16 *p_xk_hi, *p_xk_lo, *p_xv_hi, *p_xv_lo, *p_r_hi, *p_r_lo;
    __nv_bfloat16 *p_wk_hi, *p_wk_lo, *p_wv_hi, *p_wv_lo, *p_wo_hi, *p_wo_lo;
    float *p_k, *p_v;
    cudaGetSymbolAddress((void**)&p_xk_hi, g_xk_hi);
    cudaGetSymbolAddress((void**)&p_xk_lo, g_xk_lo);
    cudaGetSymbolAddress((void**)&p_xv_hi, g_xv_hi);
    cudaGetSymbolAddress((void**)&p_xv_lo, g_xv_lo);
    cudaGetSymbolAddress((void**)&p_r_hi,  g_r_hi);
    cudaGetSymbolAddress((void**)&p_r_lo,  g_r_lo);
    cudaGetSymbolAddress((void**)&p_wk_hi, g_wkt_hi);
    cudaGetSymbolAddress((void**)&p_wk_lo, g_wkt_lo);
    cudaGetSymbolAddress((void**)&p_wv_hi, g_wvt_hi);
    cudaGetSymbolAddress((void**)&p_wv_lo, g_wvt_lo);
    cudaGetSymbolAddress((void**)&p_wo_hi, g_wot_hi);
    cudaGetSymbolAddress((void**)&p_wo_lo, g_wot_lo);
    cudaGetSymbolAddress((void**)&p_k,  g_k);
    cudaGetSymbolAddress((void**)&p_v,  g_v);

    // 1) mix + split
    mix_split_kernel<<<(M_TOT*E_DIM/4)/256, 256>>>(x, tmrkv);

    // 2) weight transpose + split
    dim3 wgrid(32, 32), wblk(32, 8);
    wsplit_kernel<<<wgrid, wblk>>>(Wk,   p_wk_hi, p_wk_lo);
    wsplit_kernel<<<wgrid, wblk>>>(Wv,   p_wv_hi, p_wv_lo);
    wsplit_kernel<<<wgrid, wblk>>>(Wout, p_wo_hi, p_wo_lo);

    // 3) k = xk @ Wk ; v = xv @ Wv
    dim3 ggrid(E_DIM/BN, M_TOT/BM);
    gemm_bf16_split<<<ggrid, 256, GEMM_SMEM>>>(p_xk_hi, p_xk_lo, p_wk_hi, p_wk_lo, p_k);
    gemm_bf16_split<<<ggrid, 256, GEMM_SMEM>>>(p_xv_hi, p_xv_lo, p_wv_hi, p_wv_lo, p_v);

    // 4) scan
    scan_pass1<<<(NCHUNK*CH)/256, 256>>>(td);
    scan_pass2<<<CH/256, 256>>>(td);
    scan_pass3<<<(NCHUNK*CH)/256, 256>>>(td, tf);

    // 5) out = rwkv @ Wout
    gemm_bf16_split<<<ggrid, 256, GEMM_SMEM>>>(p_r_hi, p_r_lo, p_wo_hi, p_wo_lo, out);
}

// round 5
// speedup vs baseline: 1.1475x; 1.1475x over previous
#include <cuda_runtime.h>
#include <cuda_bf16.h>
#include <cstdint>
#include <cstddef>

#define S_LEN 2048
#define B_DIM 8
#define E_DIM 1024
#define M_TOT (S_LEN*B_DIM)      // 16384
#define CH    (B_DIM*E_DIM)      // 8192
#define NCHUNK 16
#define CLEN  (S_LEN/NCHUNK)     // 128

// ---------------- scratch (device globals; no allocation allowed) ------------
__device__ __nv_bfloat16 g_xk_hi[(size_t)M_TOT*E_DIM];
__device__ __nv_bfloat16 g_xk_lo[(size_t)M_TOT*E_DIM];
__device__ __nv_bfloat16 g_xv_hi[(size_t)M_TOT*E_DIM];
__device__ __nv_bfloat16 g_xv_lo[(size_t)M_TOT*E_DIM];
__device__ __nv_bfloat16 g_r_hi [(size_t)M_TOT*E_DIM];
__device__ __nv_bfloat16 g_r_lo [(size_t)M_TOT*E_DIM];
__device__ float g_k [(size_t)M_TOT*E_DIM];
__device__ float g_v [(size_t)M_TOT*E_DIM];
__device__ __nv_bfloat16 g_wkt_hi[(size_t)E_DIM*E_DIM];
__device__ __nv_bfloat16 g_wkt_lo[(size_t)E_DIM*E_DIM];
__device__ __nv_bfloat16 g_wvt_hi[(size_t)E_DIM*E_DIM];
__device__ __nv_bfloat16 g_wvt_lo[(size_t)E_DIM*E_DIM];
__device__ __nv_bfloat16 g_wot_hi[(size_t)E_DIM*E_DIM];
__device__ __nv_bfloat16 g_wot_lo[(size_t)E_DIM*E_DIM];
__device__ float g_agg[3*NCHUNK*CH];
__device__ float g_pre[3*NCHUNK*CH];

// ---------------- helpers ----------------------------------------------------
__device__ __forceinline__ uint32_t smem_addr(const void* p) {
    uint32_t a;
    asm("{ .reg .u64 t; cvta.to.shared.u64 t, %1; cvt.u32.u64 %0, t; }" : "=r"(a) : "l"(p));
    return a;
}
#define CP_ASYNC16(dst, src) \
    asm volatile("cp.async.cg.shared.global [%0], [%1], 16;" :: "r"(dst), "l"(src) : "memory")
#define CP_COMMIT() asm volatile("cp.async.commit_group;" ::: "memory")
#define CP_WAIT(n)  asm volatile("cp.async.wait_group %0;" :: "n"(n) : "memory")

#define LDSM4(r, addr) \
    asm volatile("ldmatrix.sync.aligned.m8n8.x4.shared.b16 {%0,%1,%2,%3}, [%4];" \
        : "=r"((r)[0]), "=r"((r)[1]), "=r"((r)[2]), "=r"((r)[3]) : "r"(addr))

__device__ __forceinline__ void mma_bf16(float c[4], const uint32_t a[4], const uint32_t b[2]) {
    asm volatile(
        "mma.sync.aligned.m16n8k16.row.col.f32.bf16.bf16.f32 "
        "{%0,%1,%2,%3}, {%4,%5,%6,%7}, {%8,%9}, {%0,%1,%2,%3};\n"
        : "+f"(c[0]), "+f"(c[1]), "+f"(c[2]), "+f"(c[3])
        : "r"(a[0]), "r"(a[1]), "r"(a[2]), "r"(a[3]), "r"(b[0]), "r"(b[1]));
}

__device__ __forceinline__ void bsplit(float v, __nv_bfloat16& h, __nv_bfloat16& l) {
    h = __float2bfloat16_rn(v);
    l = __float2bfloat16_rn(v - __bfloat162float(h));
}

// ============================================================
// 1) token mix + bf16 split
// ============================================================
__global__ void mix_split_kernel(const float* __restrict__ x,
                                 const float* __restrict__ tmrkv) {
    int i4  = blockIdx.x * blockDim.x + threadIdx.x;
    int idx = i4 * 4;
    int e   = idx & (E_DIM - 1);
    float4 xc = *(const float4*)(x + idx);
    float4 xp = make_float4(0.f, 0.f, 0.f, 0.f);
    if (idx >= CH) xp = *(const float4*)(x + idx - CH);
    float4 mk = *(const float4*)(tmrkv + E_DIM   + e);
    float4 mv = *(const float4*)(tmrkv + 2*E_DIM + e);
    float ok[4], ov[4];
    ok[0] = mk.x*xc.x + (1.f-mk.x)*xp.x;  ov[0] = mv.x*xc.x + (1.f-mv.x)*xp.x;
    ok[1] = mk.y*xc.y + (1.f-mk.y)*xp.y;  ov[1] = mv.y*xc.y + (1.f-mv.y)*xp.y;
    ok[2] = mk.z*xc.z + (1.f-mk.z)*xp.z;  ov[2] = mv.z*xc.z + (1.f-mv.z)*xp.z;
    ok[3] = mk.w*xc.w + (1.f-mk.w)*xp.w;  ov[3] = mv.w*xc.w + (1.f-mv.w)*xp.w;
    ushort4 kh, kl, vh, vl;
    __nv_bfloat16 h, l;
    bsplit(ok[0], h, l); kh.x = __bfloat16_as_ushort(h); kl.x = __bfloat16_as_ushort(l);
    bsplit(ok[1], h, l); kh.y = __bfloat16_as_ushort(h); kl.y = __bfloat16_as_ushort(l);
    bsplit(ok[2], h, l); kh.z = __bfloat16_as_ushort(h); kl.z = __bfloat16_as_ushort(l);
    bsplit(ok[3], h, l); kh.w = __bfloat16_as_ushort(h); kl.w = __bfloat16_as_ushort(l);
    bsplit(ov[0], h, l); vh.x = __bfloat16_as_ushort(h); vl.x = __bfloat16_as_ushort(l);
    bsplit(ov[1], h, l); vh.y = __bfloat16_as_ushort(h); vl.y = __bfloat16_as_ushort(l);
    bsplit(ov[2], h, l); vh.z = __bfloat16_as_ushort(h); vl.z = __bfloat16_as_ushort(l);
    bsplit(ov[3], h, l); vh.w = __bfloat16_as_ushort(h); vl.w = __bfloat16_as_ushort(l);
    *(ushort4*)((unsigned short*)g_xk_hi + idx) = kh;
    *(ushort4*)((unsigned short*)g_xk_lo + idx) = kl;
    *(ushort4*)((unsigned short*)g_xv_hi + idx) = vh;
    *(ushort4*)((unsigned short*)g_xv_lo + idx) = vl;
}

// ============================================================
// 2) weight transpose + split:  T[n][k] = split(W[k][n])
// ============================================================
__global__ void wsplit_kernel(const float* __restrict__ W,
                              __nv_bfloat16* __restrict__ Thi,
                              __nv_bfloat16* __restrict__ Tlo) {
    __shared__ float t[32][33];
    int bx = blockIdx.x * 32;   // n block
    int by = blockIdx.y * 32;   // k block
    int tx = threadIdx.x;
    for (int j = threadIdx.y; j < 32; j += 8)
        t[j][tx] = W[(size_t)(by + j) * E_DIM + bx + tx];
    __syncthreads();
    for (int j = threadIdx.y; j < 32; j += 8) {
        float v = t[tx][j];           // element (k=by+tx, n=bx+j)
        __nv_bfloat16 h, l; bsplit(v, h, l);
        size_t o = (size_t)(bx + j) * E_DIM + by + tx;
        Thi[o] = h; Tlo[o] = l;
    }
}

// ============================================================
// 3) split-bf16 GEMM: mma.sync m16n8k16 + ldmatrix + 2-stage cp.async
//    A: [M,K] bf16 hi/lo (K-major); B: [N,K] bf16 hi/lo (pre-transposed W)
// ============================================================
#define BM 128
#define BN 128
#define BK 32
#define STR 20                     // uint32 per smem row (16 data + 4 pad)
#define TILE_U (128*STR)           // 2560 u32 per operand tile
#define STAGE_U (4*TILE_U)         // Ah,Al,Bh,Bl
#define GEMM_SMEM (2*STAGE_U*4)    // 81920 bytes -> 2 CTAs/SM

__global__ void __launch_bounds__(256)
gemm_bf16_split(const __nv_bfloat16* __restrict__ Ahi, const __nv_bfloat16* __restrict__ Alo,
                const __nv_bfloat16* __restrict__ Bhi, const __nv_bfloat16* __restrict__ Blo,
                float* __restrict__ C) {
    extern __shared__ uint32_t smem[];   // [2][4][TILE_U]

    int tid  = threadIdx.x;
    int warp = tid >> 5, lane = tid & 31;
    int wm = warp & 3, wn = warp >> 2;             // 4 x 2 warps
    int bm = blockIdx.y * BM, bn = blockIdx.x * BN;

    const char* srcs[4] = {
        (const char*)(Ahi + (size_t)bm * E_DIM),
        (const char*)(Alo + (size_t)bm * E_DIM),
        (const char*)(Bhi + (size_t)bn * E_DIM),
        (const char*)(Blo + (size_t)bn * E_DIM) };
    uint32_t sbase = smem_addr(smem);

    auto load_tile = [&](int kt, int stg) {
        uint32_t dst0 = sbase + (uint32_t)stg * STAGE_U * 4;
        int koff = kt * BK * 2;    // byte offset along K
        #pragma unroll
        for (int arr = 0; arr < 4; arr++) {
            #pragma unroll
            for (int i = 0; i < 2; i++) {
                int f = tid + i*256;
                int row = f >> 2, ch = f & 3;
                uint32_t dst = dst0 + arr*TILE_U*4 + row*STR*4 + ch*16;
                const char* src = srcs[arr] + (size_t)row * (E_DIM*2) + koff + ch*16;
                CP_ASYNC16(dst, src);
            }
        }
    };

    // ---- ldmatrix lane addressing (byte offsets within an operand tile) ----
    int lm = lane & 7, lg = lane >> 3;   // lg = matrix index 0..3
    uint32_t aoff[2];
    #pragma unroll
    for (int mt = 0; mt < 2; mt++)
        aoff[mt] = (uint32_t)(((wm*32 + mt*16 + (lg & 1)*8 + lm) * STR + (lg >> 1)*4) * 4);
    uint32_t boff[4];
    #pragma unroll
    for (int j = 0; j < 4; j++)
        boff[j] = (uint32_t)(((wn*64 + j*16 + (lg >> 1)*8 + lm) * STR + (lg & 1)*4) * 4);

    float acc[2][8][4];
    #pragma unroll
    for (int mt = 0; mt < 2; mt++)
        #pragma unroll
        for (int nt = 0; nt < 8; nt++)
            #pragma unroll
            for (int q = 0; q < 4; q++) acc[mt][nt][q] = 0.f;

    const int NK = E_DIM / BK;   // 32
    load_tile(0, 0); CP_COMMIT();

    for (int kt = 0; kt < NK; kt++) {
        int buf = kt & 1;
        if (kt + 1 < NK) { load_tile(kt+1, buf ^ 1); CP_COMMIT(); CP_WAIT(1); }
        else             { CP_WAIT(0); }
        __syncthreads();

        uint32_t tAh = sbase + (uint32_t)buf * STAGE_U * 4;
        uint32_t tAl = tAh + TILE_U*4;
        uint32_t tBh = tAh + 2*TILE_U*4;
        uint32_t tBl = tAh + 3*TILE_U*4;

        #pragma unroll
        for (int ks = 0; ks < 2; ks++) {
            uint32_t ksb = (uint32_t)(ks * 8 * 4);
            uint32_t ah[2][4], al[2][4], bh[8][2], bl[8][2];
            #pragma unroll
            for (int mt = 0; mt < 2; mt++) {
                LDSM4(ah[mt], tAh + aoff[mt] + ksb);
                LDSM4(al[mt], tAl + aoff[mt] + ksb);
            }
            #pragma unroll
            for (int j = 0; j < 4; j++) {
                uint32_t rb[4], rl[4];
                LDSM4(rb, tBh + boff[j] + ksb);
                bh[2*j][0] = rb[0]; bh[2*j][1] = rb[1];
                bh[2*j+1][0] = rb[2]; bh[2*j+1][1] = rb[3];
                LDSM4(rl, tBl + boff[j] + ksb);
                bl[2*j][0] = rl[0]; bl[2*j][1] = rl[1];
                bl[2*j+1][0] = rl[2]; bl[2*j+1][1] = rl[3];
            }
            #pragma unroll
            for (int mt = 0; mt < 2; mt++)
                #pragma unroll
                for (int nt = 0; nt < 8; nt++) {
                    mma_bf16(acc[mt][nt], ah[mt], bh[nt]);
                    mma_bf16(acc[mt][nt], ah[mt], bl[nt]);
                    mma_bf16(acc[mt][nt], al[mt], bh[nt]);
                }
        }
        __syncthreads();
    }

    #pragma unroll
    for (int mt = 0; mt < 2; mt++) {
        int r0 = bm + wm*32 + mt*16 + (lane >> 2);
        #pragma unroll
        for (int nt = 0; nt < 8; nt++) {
            int c0 = bn + wn*64 + nt*8 + ((lane & 3) << 1);
            *(float2*)(&C[(size_t) r0     *E_DIM + c0]) = make_float2(acc[mt][nt][0], acc[mt][nt][1]);
            *(float2*)(&C[(size_t)(r0 + 8)*E_DIM + c0]) = make_float2(acc[mt][nt][2], acc[mt][nt][3]);
        }
    }
}

// ============================================================
// 4) chunked associative exp-scan
// ============================================================
__global__ void scan_pass1(const float* __restrict__ time_decay) {
    int tid = blockIdx.x * blockDim.x + threadIdx.x;
    int c = tid / CH, ch = tid % CH;
    float w = time_decay[ch & (E_DIM - 1)];
    float a = 0.f, b = 0.f, p = -1e30f;
    int base = c * CLEN;
    for (int t0 = 0; t0 < CLEN; t0 += 8) {
        float kk[8], vv[8];
        #pragma unroll
        for (int i = 0; i < 8; i++) {
            size_t off = (size_t)(base + t0 + i) * CH + ch;
            kk[i] = g_k[off]; vv[i] = g_v[off];
        }
        #pragma unroll
        for (int i = 0; i < 8; i++) {
            float pw = p + w;
            float d  = pw - kk[i];
            float e  = __expf(-fabsf(d));
            float e1 = (d >= 0.f) ? 1.f : e;
            float e2 = (d >= 0.f) ? e   : 1.f;
            a = a*e1 + vv[i]*e2;
            b = b*e1 + e2;
            p = fmaxf(pw, kk[i]);
        }
    }
    g_agg[              c*CH + ch] = a;
    g_agg[  NCHUNK*CH + c*CH + ch] = b;
    g_agg[2*NCHUNK*CH + c*CH + ch] = p;
}

__global__ void scan_pass2(const float* __restrict__ time_decay) {
    int ch = blockIdx.x * blockDim.x + threadIdx.x;
    float w  = time_decay[ch & (E_DIM - 1)];
    float Lw = (float)CLEN * w;
    float a = 0.f, b = 0.f, p = -1e30f;
    for (int c = 0; c < NCHUNK; c++) {
        g_pre[              c*CH + ch] = a;
        g_pre[  NCHUNK*CH + c*CH + ch] = b;
        g_pre[2*NCHUNK*CH + c*CH + ch] = p;
        float a2 = g_agg[              c*CH + ch];
        float b2 = g_agg[  NCHUNK*CH + c*CH + ch];
        float p2 = g_agg[2*NCHUNK*CH + c*CH + ch];
        float pw = p + Lw;
        float d  = pw - p2;
        float e  = __expf(-fabsf(d));
        float e1 = (d >= 0.f) ? 1.f : e;
        float e2 = (d >= 0.f) ? e   : 1.f;
        a = a*e1 + a2*e2;
        b = b*e1 + b2*e2;
        p = fmaxf(pw, p2);
    }
}

__global__ void scan_pass3(const float* __restrict__ time_decay,
                           const float* __restrict__ time_first) {
    int tid = blockIdx.x * blockDim.x + threadIdx.x;
    int c = tid / CH, ch = tid % CH;
    int e0 = ch & (E_DIM - 1);
    float w = time_decay[e0];
    float u = time_first[e0];
    float a = g_pre[              c*CH + ch];
    float b = g_pre[  NCHUNK*CH + c*CH + ch];
    float p = g_pre[2*NCHUNK*CH + c*CH + ch];
    int base = c * CLEN;
    for (int t0 = 0; t0 < CLEN; t0 += 8) {
        float kk[8], vv[8];
        #pragma unroll
        for (int i = 0; i < 8; i++) {
            size_t off = (size_t)(base + t0 + i) * CH + ch;
            kk[i] = g_k[off]; vv[i] = g_v[off];
        }
        #pragma unroll
        for (int i = 0; i < 8; i++) {
            float pw = p + w;
            float d  = pw - kk[i];
            float e  = __expf(-fabsf(d));
            float e1 = (d >= 0.f) ? 1.f : e;
            float e2 = (d >= 0.f) ? e   : 1.f;
            a = a*e1 + vv[i]*e2;
            b = b*e1 + e2;
            p = fmaxf(pw, kk[i]);
            float kb = kk[i] + u + w;
            float d2 = p - kb;
            float eo = __expf(-fabsf(d2));
            float o1 = (d2 >= 0.f) ? 1.f : eo;
            float o2 = (d2 >= 0.f) ? eo  : 1.f;
            float cn = a*o1 + vv[i]*o2;
            float dn = b*o1 + o2;
            float q  = __fdividef(cn, dn);
            size_t off = (size_t)(base + t0 + i) * CH + ch;
            __nv_bfloat16 h, l; bsplit(q, h, l);
            g_r_hi[off] = h; g_r_lo[off] = l;
        }
    }
}

// ============================================================
// launch
// ============================================================
extern "C" void kernel_launch(void* const* d_in, const int* in_sizes, int n_in,
                              void* d_out, int out_size) {
    const float* x     = (const float*)d_in[0];
    const float* tmrkv = (const float*)d_in[1];
    const float* Wk    = (const float*)d_in[2];
    const float* Wv    = (const float*)d_in[3];
    const float* td    = (const float*)d_in[4];
    const float* tf    = (const float*)d_in[5];
    const float* Wout  = (const float*)d_in[6];
    float* out = (float*)d_out;

    cudaFuncSetAttribute(gemm_bf16_split,
                         cudaFuncAttributeMaxDynamicSharedMemorySize, GEMM_SMEM);

    __nv_bfloat16 *p_xk_hi, *p_xk_lo, *p_xv_hi, *p_xv_lo, *p_r_hi, *p_r_lo;
    __nv_bfloat16 *p_wk_hi, *p_wk_lo, *p_wv_hi, *p_wv_lo, *p_wo_hi, *p_wo_lo;
    float *p_k, *p_v;
    cudaGetSymbolAddress((void**)&p_xk_hi, g_xk_hi);
    cudaGetSymbolAddress((void**)&p_xk_lo, g_xk_lo);
    cudaGetSymbolAddress((void**)&p_xv_hi, g_xv_hi);
    cudaGetSymbolAddress((void**)&p_xv_lo, g_xv_lo);
    cudaGetSymbolAddress((void**)&p_r_hi,  g_r_hi);
    cudaGetSymbolAddress((void**)&p_r_lo,  g_r_lo);
    cudaGetSymbolAddress((void**)&p_wk_hi, g_wkt_hi);
    cudaGetSymbolAddress((void**)&p_wk_lo, g_wkt_lo);
    cudaGetSymbolAddress((void**)&p_wv_hi, g_wvt_hi);
    cudaGetSymbolAddress((void**)&p_wv_lo, g_wvt_lo);
    cudaGetSymbolAddress((void**)&p_wo_hi, g_wot_hi);
    cudaGetSymbolAddress((void**)&p_wo_lo, g_wot_lo);
    cudaGetSymbolAddress((void**)&p_k,  g_k);
    cudaGetSymbolAddress((void**)&p_v,  g_v);

    // 1) mix + split
    mix_split_kernel<<<(M_TOT*E_DIM/4)/256, 256>>>(x, tmrkv);

    // 2) weight transpose + split
    dim3 wgrid(32, 32), wblk(32, 8);
    wsplit_kernel<<<wgrid, wblk>>>(Wk,   p_wk_hi, p_wk_lo);
    wsplit_kernel<<<wgrid, wblk>>>(Wv,   p_wv_hi, p_wv_lo);
    wsplit_kernel<<<wgrid, wblk>>>(Wout, p_wo_hi, p_wo_lo);

    // 3) k = xk @ Wk ; v = xv @ Wv
    dim3 ggrid(E_DIM/BN, M_TOT/BM);
    gemm_bf16_split<<<ggrid, 256, GEMM_SMEM>>>(p_xk_hi, p_xk_lo, p_wk_hi, p_wk_lo, p_k);
    gemm_bf16_split<<<ggrid, 256, GEMM_SMEM>>>(p_xv_hi, p_xv_lo, p_wv_hi, p_wv_lo, p_v);

    // 4) scan
    scan_pass1<<<(NCHUNK*CH)/256, 256>>>(td);
    scan_pass2<<<CH/256, 256>>>(td);
    scan_pass3<<<(NCHUNK*CH)/256, 256>>>(td, tf);

    // 5) out = rwkv @ Wout
    gemm_bf16_split<<<ggrid, 256, GEMM_SMEM>>>(p_r_hi, p_r_lo, p_wo_hi, p_wo_lo, out);
}